// round 2
// baseline (speedup 1.0000x reference)
#include <cuda_runtime.h>
#include <cstdint>

#define BATCH 32
#define SEQ_LEN 4096
#define D_MODEL 256
#define STATE_N 64
#define N_CLASSES 5
#define C_CHUNKS 16
#define T_CHUNK (SEQ_LEN / C_CHUNKS)   /* 256 */
#define NPAIR 16                       /* f32x2 pairs per thread -> 32 states */

// Scratch (no cudaMalloc allowed): chunk-boundary states + per-chunk pool partials
__device__ float g_scratch[BATCH * C_CHUNKS * D_MODEL * STATE_N];  // 33.5 MB
__device__ float g_pool[BATCH * D_MODEL * C_CHUNKS * 2];           // 1 MB

typedef unsigned long long ull;

__device__ __forceinline__ ull pk2(float lo, float hi) {
    ull r; asm("mov.b64 %0, {%1, %2};" : "=l"(r) : "f"(lo), "f"(hi)); return r;
}
__device__ __forceinline__ void upk2(ull v, float &lo, float &hi) {
    asm("mov.b64 {%0, %1}, %2;" : "=f"(lo), "=f"(hi) : "l"(v));
}
__device__ __forceinline__ ull ffma2(ull a, ull b, ull c) {
    ull d; asm("fma.rn.f32x2 %0, %1, %2, %3;" : "=l"(d) : "l"(a), "l"(b), "l"(c)); return d;
}
__device__ __forceinline__ ull fmul2(ull a, ull b) {
    ull d; asm("mul.rn.f32x2 %0, %1, %2;" : "=l"(d) : "l"(a), "l"(b)); return d;
}
__device__ __forceinline__ ull fadd2(ull a, ull b) {
    ull d; asm("add.rn.f32x2 %0, %1, %2;" : "=l"(d) : "l"(a), "l"(b)); return d;
}

// ---------------- Pass 1: per-chunk local final states (zero-seeded) ----------------
__global__ __launch_bounds__(256, 2)
void pass1_chunk_states(const float* __restrict__ x,
                        const float* __restrict__ w_in,
                        const float* __restrict__ b_in,
                        const float* __restrict__ A_diag) {
    __shared__ float shx[T_CHUNK];
    const int c = blockIdx.x, dh = blockIdx.y, b = blockIdx.z;
    const int tid = threadIdx.x;
    const int d = dh * 128 + (tid >> 1);
    const int half = tid & 1;
    shx[tid] = x[b * SEQ_LEN + c * T_CHUNK + tid];

    const float2* A2 = reinterpret_cast<const float2*>(A_diag + d * STATE_N + half * 32);
    ull a2[NPAIR];
    #pragma unroll
    for (int j = 0; j < NPAIR; j++) { float2 v = A2[j]; a2[j] = pk2(v.x, v.y); }
    const float w = w_in[d], bi = b_in[d];
    __syncthreads();

    ull r[NPAIR];
    #pragma unroll
    for (int j = 0; j < NPAIR; j++) r[j] = 0ull;

    #pragma unroll 4
    for (int t = 0; t < T_CHUNK; t++) {
        float u = fmaf(shx[t], w, bi);
        ull u2 = pk2(u, u);
        #pragma unroll
        for (int j = 0; j < NPAIR; j++) r[j] = ffma2(a2[j], r[j], u2);
    }
    float2* outp = reinterpret_cast<float2*>(
        g_scratch + ((size_t)(b * C_CHUNKS + c) * D_MODEL + d) * STATE_N + half * 32);
    #pragma unroll
    for (int j = 0; j < NPAIR; j++) { float2 o; upk2(r[j], o.x, o.y); outp[j] = o; }
}

// ---------------- Pass 2: inter-chunk scan, converts local finals -> chunk seeds ----------------
__global__ void pass2_scan(const float* __restrict__ A_diag) {
    int i = blockIdx.x * blockDim.x + threadIdx.x;  // < B*D*N
    int b = i >> 14;          // D*N = 16384
    int rem = i & 16383;
    int d = rem >> 6;
    int n = rem & 63;
    float a = A_diag[d * STATE_N + n];
    float aL = a;
    #pragma unroll
    for (int k = 0; k < 8; k++) aL *= aL;   // a^256 = a^T_CHUNK
    float r = 0.f;                          // true state at start of chunk 0
    int idx = b * (C_CHUNKS * D_MODEL * STATE_N) + d * STATE_N + n;
    #pragma unroll
    for (int c = 0; c < C_CHUNKS; c++) {
        float f = g_scratch[idx];           // local final of chunk c
        g_scratch[idx] = r;                 // seed for chunk c
        r = fmaf(aL, r, f);                 // true state at start of chunk c+1
        idx += D_MODEL * STATE_N;
    }
}

// ---------------- Pass 3: seeded recurrence + readout + gelu + chunk pooling ----------------
__global__ __launch_bounds__(256, 2)
void pass3_main(const float* __restrict__ x,
                const float* __restrict__ w_in,
                const float* __restrict__ b_in,
                const float* __restrict__ A_diag,
                const float* __restrict__ B_in,
                const float* __restrict__ C_out,
                const float* __restrict__ D_skip) {
    __shared__ float shx[T_CHUNK];
    const int c = blockIdx.x, dh = blockIdx.y, b = blockIdx.z;
    const int tid = threadIdx.x;
    const int d = dh * 128 + (tid >> 1);
    const int half = tid & 1;
    shx[tid] = x[b * SEQ_LEN + c * T_CHUNK + tid];

    const float2* A2 = reinterpret_cast<const float2*>(A_diag + d * STATE_N + half * 32);
    const float2* B2 = reinterpret_cast<const float2*>(B_in  + d * STATE_N + half * 32);
    const float2* C2 = reinterpret_cast<const float2*>(C_out + d * STATE_N + half * 32);
    ull a2[NPAIR], gg[NPAIR];
    #pragma unroll
    for (int j = 0; j < NPAIR; j++) {
        float2 av = A2[j]; float2 bv = B2[j]; float2 cv = C2[j];
        a2[j] = pk2(av.x, av.y);
        gg[j] = pk2(bv.x * cv.x, bv.y * cv.y);   // g_n = C_n * B_n (state rescale trick)
    }
    const float w = w_in[d], bi = b_in[d], dsk = D_skip[d];

    const float2* seedp = reinterpret_cast<const float2*>(
        g_scratch + ((size_t)(b * C_CHUNKS + c) * D_MODEL + d) * STATE_N + half * 32);
    ull r[NPAIR];
    #pragma unroll
    for (int j = 0; j < NPAIR; j++) { float2 sv = seedp[j]; r[j] = pk2(sv.x, sv.y); }
    __syncthreads();

    float psum = 0.f;
    float pmax = -3.402823466e38f;

    #pragma unroll 2
    for (int t = 0; t < T_CHUNK; t++) {
        float u = fmaf(shx[t], w, bi);
        ull u2 = pk2(u, u);
        #pragma unroll
        for (int j = 0; j < NPAIR; j++) r[j] = ffma2(a2[j], r[j], u2);
        ull acc0 = fmul2(gg[0], r[0]);
        ull acc1 = fmul2(gg[1], r[1]);
        ull acc2 = fmul2(gg[2], r[2]);
        ull acc3 = fmul2(gg[3], r[3]);
        #pragma unroll
        for (int j = 4; j < NPAIR; j += 4) {
            acc0 = ffma2(gg[j+0], r[j+0], acc0);
            acc1 = ffma2(gg[j+1], r[j+1], acc1);
            acc2 = ffma2(gg[j+2], r[j+2], acc2);
            acc3 = ffma2(gg[j+3], r[j+3], acc3);
        }
        acc0 = fadd2(acc0, acc1);
        acc2 = fadd2(acc2, acc3);
        acc0 = fadd2(acc0, acc2);
        float lo, hi; upk2(acc0, lo, hi);
        float yp = lo + hi;
        yp += __shfl_xor_sync(0xffffffffu, yp, 1);   // join the two n-halves
        float ypre = fmaf(dsk, u, yp);
        // jax.nn.gelu approximate=True: 0.5*x*(1+tanh(sqrt(2/pi)*(x+0.044715 x^3)))
        float inner = 0.7978845608028654f * ypre * fmaf(0.044715f, ypre * ypre, 1.0f);
        float th; asm("tanh.approx.f32 %0, %1;" : "=f"(th) : "f"(inner));
        float h = 0.5f * ypre * (1.0f + th);
        psum += h;
        pmax = fmaxf(pmax, h);
    }
    if (half == 0) {
        float* pp = g_pool + ((size_t)(b * D_MODEL + d) * C_CHUNKS + c) * 2;
        pp[0] = psum;
        pp[1] = pmax;
    }
}

// ---------------- Pass 4: pool across chunks + head matmul ----------------
__global__ void pass4_head(const float* __restrict__ W_head,
                           const float* __restrict__ b_head,
                           float* __restrict__ out) {
    const int b = blockIdx.x;
    const int d = threadIdx.x;   // 256 threads
    const float* pp = g_pool + ((size_t)(b * D_MODEL + d)) * C_CHUNKS * 2;
    float s = 0.f, m = -3.402823466e38f;
    #pragma unroll
    for (int c = 0; c < C_CHUNKS; c++) { s += pp[2 * c]; m = fmaxf(m, pp[2 * c + 1]); }
    float avg = s * (1.0f / (float)SEQ_LEN);
    float contrib[N_CLASSES];
    #pragma unroll
    for (int k = 0; k < N_CLASSES; k++)
        contrib[k] = avg * W_head[d * N_CLASSES + k]
                   + m   * W_head[(D_MODEL + d) * N_CLASSES + k];
    __shared__ float red[8][N_CLASSES];
    int lane = d & 31, wid = d >> 5;
    #pragma unroll
    for (int k = 0; k < N_CLASSES; k++) {
        float v = contrib[k];
        #pragma unroll
        for (int o = 16; o > 0; o >>= 1) v += __shfl_xor_sync(0xffffffffu, v, o);
        if (lane == 0) red[wid][k] = v;
    }
    __syncthreads();
    if (d == 0) {
        #pragma unroll
        for (int k = 0; k < N_CLASSES; k++) {
            float t = b_head[k];
            #pragma unroll
            for (int wq = 0; wq < 8; wq++) t += red[wq][k];
            out[b * N_CLASSES + k] = t;
        }
    }
}

extern "C" void kernel_launch(void* const* d_in, const int* in_sizes, int n_in,
                              void* d_out, int out_size) {
    const float* x      = (const float*)d_in[0];
    const float* w_in   = (const float*)d_in[1];
    const float* b_in   = (const float*)d_in[2];
    const float* A_diag = (const float*)d_in[3];
    const float* B_in   = (const float*)d_in[4];
    const float* C_out  = (const float*)d_in[5];
    const float* D_skip = (const float*)d_in[6];
    const float* W_head = (const float*)d_in[7];
    const float* b_head = (const float*)d_in[8];
    float* out = (float*)d_out;

    dim3 g13(C_CHUNKS, 2, BATCH);
    pass1_chunk_states<<<g13, 256>>>(x, w_in, b_in, A_diag);
    pass2_scan<<<(BATCH * D_MODEL * STATE_N) / 256, 256>>>(A_diag);
    pass3_main<<<g13, 256>>>(x, w_in, b_in, A_diag, B_in, C_out, D_skip);
    pass4_head<<<BATCH, 256>>>(W_head, b_head, out);
}